// round 3
// baseline (speedup 1.0000x reference)
#include <cuda_runtime.h>
#include <math.h>

// Problem constants
#define BB 8
#define NN 65536
#define CC 1024
#define H0V 128
#define H1V 256
#define BN (BB*NN)       // 524288 points
#define TP 64            // points per block

// ---------------------------------------------------------------------------
// Scratch (device globals: allocation-free rule)
// ---------------------------------------------------------------------------
__device__ __align__(16) float g_x1[(size_t)BN * H0V];     // 268 MB: conv1 output per point
__device__ __align__(16) float g_y1[(size_t)BB * CC * H0V]; // 4 MB: scatter-max of x1
__device__ __align__(16) float g_z [(size_t)BB * CC * H1V]; // 8 MB: y1 @ w3_top + b3
__device__ int g_idx64;                                     // nn_idx dtype flag

// ---------------------------------------------------------------------------
// nn_idx dtype detection: int64 buffers have zero high words at odd int32 slots
// ---------------------------------------------------------------------------
__global__ void k_detect(const void* nn)
{
    if (threadIdx.x == 0 && blockIdx.x == 0) {
        const int* p = (const int*)nn;
        int allzero = 1;
        #pragma unroll 1
        for (int s = 0; s < 64; s++) {
            int i = (int)(((long long)s * 4099) % (BN / 2)); // stays in-bounds for int32 case
            if (p[2 * i + 1] != 0) { allzero = 0; break; }
        }
        g_idx64 = allzero;
    }
}

__device__ __forceinline__ int load_idx(const void* nn, int i)
{
    if (g_idx64) return (int)((const long long*)nn)[i];
    return ((const int*)nn)[i];
}

// ---------------------------------------------------------------------------
// Zero init: d_out (8 MB) and g_y1 (4 MB)
// ---------------------------------------------------------------------------
__global__ void k_zero(float* __restrict__ out)
{
    int i = blockIdx.x * blockDim.x + threadIdx.x;
    int stride = gridDim.x * blockDim.x;
    float4 z = make_float4(0.f, 0.f, 0.f, 0.f);
    const int n_out = BB * CC * H1V / 4;
    for (int j = i; j < n_out; j += stride) ((float4*)out)[j] = z;
    const int n_y = BB * CC * H0V / 4;
    for (int j = i; j < n_y; j += stride) ((float4*)g_y1)[j] = z;
}

__device__ __forceinline__ float gelu_exact(float t)
{
    return 0.5f * t * (1.f + erff(t * 0.70710678118654752f));
}

// ---------------------------------------------------------------------------
// K1: conv1 MLP per 64-point tile: (p@w1+b1) -> LN -> GELU -> @w2+b2
//     writes g_x1, atomicMax into g_y1
// smem: w2[128*128] | a[64*128] | p[64*8] | w1[6*128] | b1,g1,be1,b2 | idx[64]
// ---------------------------------------------------------------------------
#define K1_SMEM ((26368 + 64) * 4)
__global__ void __launch_bounds__(256, 2) k_conv1(
    const float* __restrict__ patches, const void* __restrict__ nn,
    const float* __restrict__ w1, const float* __restrict__ b1,
    const float* __restrict__ g1, const float* __restrict__ be1,
    const float* __restrict__ w2, const float* __restrict__ b2)
{
    extern __shared__ __align__(16) float sm[];
    float* s_w2  = sm;             // 16384
    float* s_a   = sm + 16384;     // 8192
    float* s_p   = sm + 24576;     // 512
    float* s_w1  = sm + 25088;     // 768
    float* s_b1  = sm + 25856;     // 128
    float* s_g1  = sm + 25984;     // 128
    float* s_be1 = sm + 26112;     // 128
    float* s_b2  = sm + 26240;     // 128
    int*   s_idx = (int*)(sm + 26368); // 64

    const int tid = threadIdx.x;
    const int p0  = blockIdx.x * TP;

    for (int i = tid; i < 4096; i += 256) ((float4*)s_w2)[i] = ((const float4*)w2)[i];
    for (int i = tid; i < 768; i += 256) s_w1[i] = w1[i];
    if (tid < 128) {
        s_b1[tid] = b1[tid]; s_g1[tid] = g1[tid];
        s_be1[tid] = be1[tid]; s_b2[tid] = b2[tid];
    }
    for (int i = tid; i < TP * 6; i += 256) {
        int r = i / 6, c = i % 6;
        s_p[r * 8 + c] = patches[(size_t)(p0 + r) * 6 + c];
    }
    if (tid < TP) s_idx[tid] = load_idx(nn, p0 + tid);
    __syncthreads();

    // h = p @ w1 + b1
    for (int e = tid; e < TP * 128; e += 256) {
        int r = e >> 7, c = e & 127;
        float acc = s_b1[c];
        #pragma unroll
        for (int k = 0; k < 6; k++) acc = fmaf(s_p[r * 8 + k], s_w1[k * 128 + c], acc);
        s_a[e] = acc;
    }
    __syncthreads();

    // LayerNorm(128) + GELU, one warp per 8 rows
    const int warp = tid >> 5, lane = tid & 31;
    for (int rr = 0; rr < 8; rr++) {
        int r = warp * 8 + rr;
        float v[4], s = 0.f, s2 = 0.f;
        #pragma unroll
        for (int j = 0; j < 4; j++) {
            v[j] = s_a[r * 128 + lane + 32 * j];
            s += v[j]; s2 = fmaf(v[j], v[j], s2);
        }
        #pragma unroll
        for (int o = 16; o; o >>= 1) {
            s  += __shfl_xor_sync(0xffffffffu, s,  o);
            s2 += __shfl_xor_sync(0xffffffffu, s2, o);
        }
        float mu  = s * (1.f / 128.f);
        float var = s2 * (1.f / 128.f) - mu * mu;
        float rstd = rsqrtf(var + 1e-5f);
        #pragma unroll
        for (int j = 0; j < 4; j++) {
            int c = lane + 32 * j;
            float t = (v[j] - mu) * rstd * s_g1[c] + s_be1[c];
            s_a[r * 128 + c] = gelu_exact(t);
        }
    }
    __syncthreads();

    // X1 = A @ w2 + b2 ; thread tile: rows warp*8..+7, cols lane*4..+3
    float acc[8][4];
    {
        float4 bv = *(const float4*)&s_b2[lane * 4];
        #pragma unroll
        for (int i = 0; i < 8; i++) {
            acc[i][0] = bv.x; acc[i][1] = bv.y; acc[i][2] = bv.z; acc[i][3] = bv.w;
        }
    }
    #pragma unroll 8
    for (int k = 0; k < 128; k++) {
        float4 wv = *(const float4*)&s_w2[k * 128 + lane * 4];
        #pragma unroll
        for (int i = 0; i < 8; i++) {
            float a = s_a[(warp * 8 + i) * 128 + k];
            acc[i][0] = fmaf(a, wv.x, acc[i][0]);
            acc[i][1] = fmaf(a, wv.y, acc[i][1]);
            acc[i][2] = fmaf(a, wv.z, acc[i][2]);
            acc[i][3] = fmaf(a, wv.w, acc[i][3]);
        }
    }

    const int b = p0 >> 16; // p0 / N
    #pragma unroll
    for (int i = 0; i < 8; i++) {
        int r = warp * 8 + i;
        float4 o = make_float4(acc[i][0], acc[i][1], acc[i][2], acc[i][3]);
        *(float4*)&g_x1[(size_t)(p0 + r) * 128 + lane * 4] = o;
        int ci = s_idx[r];
        int* yb = (int*)&g_y1[((size_t)b * CC + ci) * 128 + lane * 4];
        #pragma unroll
        for (int j = 0; j < 4; j++) {
            float v = acc[i][j];
            if (v > 0.f) atomicMax(yb + j, __float_as_int(v));
        }
    }
}

// ---------------------------------------------------------------------------
// Kz: g_z = g_y1 @ w3[0:128,:] + b3   (per-center hoist of the x_max GEMM)
// smem: y[64*128] | w[32*256] | b3[256]
// ---------------------------------------------------------------------------
#define KZ_SMEM (16640 * 4)
__global__ void __launch_bounds__(256, 2) k_center(
    const float* __restrict__ w3, const float* __restrict__ b3)
{
    extern __shared__ __align__(16) float sm[];
    float* s_y  = sm;          // 8192
    float* s_w  = sm + 8192;   // 8192
    float* s_b3 = sm + 16384;  // 256

    const int tid = threadIdx.x;
    const int bc0 = blockIdx.x * 64;

    for (int i = tid; i < 2048; i += 256)
        ((float4*)s_y)[i] = ((const float4*)(g_y1 + (size_t)bc0 * 128))[i];
    s_b3[tid & 255] = b3[tid & 255];

    const int warp = tid >> 5, lane = tid & 31;
    float acc[8][8];
    #pragma unroll
    for (int i = 0; i < 8; i++)
        #pragma unroll
        for (int j = 0; j < 8; j++) acc[i][j] = 0.f;

    for (int kc = 0; kc < 4; kc++) {
        __syncthreads();
        for (int i = tid; i < 2048; i += 256)
            ((float4*)s_w)[i] = ((const float4*)(w3 + (size_t)(kc * 32) * 256))[i];
        __syncthreads();
        #pragma unroll 8
        for (int k = 0; k < 32; k++) {
            float4 w0 = *(const float4*)&s_w[k * 256 + lane * 4];
            float4 w1v = *(const float4*)&s_w[k * 256 + 128 + lane * 4];
            #pragma unroll
            for (int i = 0; i < 8; i++) {
                float a = s_y[(warp * 8 + i) * 128 + kc * 32 + k];
                acc[i][0] = fmaf(a, w0.x, acc[i][0]);
                acc[i][1] = fmaf(a, w0.y, acc[i][1]);
                acc[i][2] = fmaf(a, w0.z, acc[i][2]);
                acc[i][3] = fmaf(a, w0.w, acc[i][3]);
                acc[i][4] = fmaf(a, w1v.x, acc[i][4]);
                acc[i][5] = fmaf(a, w1v.y, acc[i][5]);
                acc[i][6] = fmaf(a, w1v.z, acc[i][6]);
                acc[i][7] = fmaf(a, w1v.w, acc[i][7]);
            }
        }
    }
    #pragma unroll
    for (int i = 0; i < 8; i++) {
        int r = warp * 8 + i;
        size_t zo = (size_t)(bc0 + r) * 256;
        float4 o0 = make_float4(acc[i][0] + s_b3[lane * 4 + 0],
                                acc[i][1] + s_b3[lane * 4 + 1],
                                acc[i][2] + s_b3[lane * 4 + 2],
                                acc[i][3] + s_b3[lane * 4 + 3]);
        float4 o1 = make_float4(acc[i][4] + s_b3[128 + lane * 4 + 0],
                                acc[i][5] + s_b3[128 + lane * 4 + 1],
                                acc[i][6] + s_b3[128 + lane * 4 + 2],
                                acc[i][7] + s_b3[128 + lane * 4 + 3]);
        *(float4*)&g_z[zo + lane * 4] = o0;
        *(float4*)&g_z[zo + 128 + lane * 4] = o1;
    }
}

// ---------------------------------------------------------------------------
// K2: per 64-point tile:
//   h = x1 @ w3[128:256,:] + gathered z  -> LN -> GELU -> @w4 + b4 -> atomicMax
// smem regions: A[32*256] (x1 tile / h rows 0-31) | W[32*256] | Bh[32*256]
// ---------------------------------------------------------------------------
#define K2_SMEM ((25344 + 64) * 4)
__global__ void __launch_bounds__(256, 2) k_conv2(
    const void* __restrict__ nn,
    const float* __restrict__ w3, const float* __restrict__ g2,
    const float* __restrict__ be2, const float* __restrict__ w4,
    const float* __restrict__ b4, float* __restrict__ out)
{
    extern __shared__ __align__(16) float sm[];
    float* sA    = sm;            // 8192: x1 tile (64x128) / h rows 0-31
    float* sW    = sm + 8192;     // 8192: weight k-chunk (32x256)
    float* sBh   = sm + 16384;    // 8192: h rows 32-63
    float* s_g2  = sm + 24576;    // 256
    float* s_be2 = sm + 24832;    // 256
    float* s_b4  = sm + 25088;    // 256
    int*   s_idx = (int*)(sm + 25344); // 64

    const int tid = threadIdx.x;
    const int p0  = blockIdx.x * TP;
    const int b   = p0 >> 16;

    for (int i = tid; i < 2048; i += 256)
        ((float4*)sA)[i] = ((const float4*)(g_x1 + (size_t)p0 * 128))[i];
    if (tid < 64) s_idx[tid] = load_idx(nn, p0 + tid);
    s_g2[tid & 255] = g2[tid & 255];
    s_be2[tid & 255] = be2[tid & 255];
    s_b4[tid & 255] = b4[tid & 255];
    __syncthreads();

    const int warp = tid >> 5, lane = tid & 31;

    // acc init = gathered z row (already contains b3 and the x_max contribution)
    float acc[8][8];
    #pragma unroll
    for (int i = 0; i < 8; i++) {
        int r = warp * 8 + i;
        const float* zr = g_z + ((size_t)b * CC + s_idx[r]) * 256;
        float4 z0 = *(const float4*)&zr[lane * 4];
        float4 z1 = *(const float4*)&zr[128 + lane * 4];
        acc[i][0] = z0.x; acc[i][1] = z0.y; acc[i][2] = z0.z; acc[i][3] = z0.w;
        acc[i][4] = z1.x; acc[i][5] = z1.y; acc[i][6] = z1.z; acc[i][7] = z1.w;
    }

    // GEMM1: += x1 @ w3_bot  (k = 128 in 4 chunks of 32)
    for (int kc = 0; kc < 4; kc++) {
        __syncthreads();
        for (int i = tid; i < 2048; i += 256)
            ((float4*)sW)[i] = ((const float4*)(w3 + (size_t)(128 + kc * 32) * 256))[i];
        __syncthreads();
        #pragma unroll 8
        for (int k = 0; k < 32; k++) {
            float4 w0 = *(const float4*)&sW[k * 256 + lane * 4];
            float4 w1v = *(const float4*)&sW[k * 256 + 128 + lane * 4];
            #pragma unroll
            for (int i = 0; i < 8; i++) {
                float a = sA[(warp * 8 + i) * 128 + kc * 32 + k];
                acc[i][0] = fmaf(a, w0.x, acc[i][0]);
                acc[i][1] = fmaf(a, w0.y, acc[i][1]);
                acc[i][2] = fmaf(a, w0.z, acc[i][2]);
                acc[i][3] = fmaf(a, w0.w, acc[i][3]);
                acc[i][4] = fmaf(a, w1v.x, acc[i][4]);
                acc[i][5] = fmaf(a, w1v.y, acc[i][5]);
                acc[i][6] = fmaf(a, w1v.z, acc[i][6]);
                acc[i][7] = fmaf(a, w1v.w, acc[i][7]);
            }
        }
    }
    __syncthreads();

    // stash h into sA (rows 0-31) / sBh (rows 32-63)
    float* hb[8];
    #pragma unroll
    for (int i = 0; i < 8; i++) {
        int r = warp * 8 + i;
        hb[i] = (r < 32) ? (sA + r * 256) : (sBh + (r - 32) * 256);
        *(float4*)&hb[i][lane * 4] = make_float4(acc[i][0], acc[i][1], acc[i][2], acc[i][3]);
        *(float4*)&hb[i][128 + lane * 4] = make_float4(acc[i][4], acc[i][5], acc[i][6], acc[i][7]);
    }
    __syncthreads();

    // LayerNorm(256) + GELU in place
    for (int rr = 0; rr < 8; rr++) {
        int r = warp * 8 + rr;
        float* hr = (r < 32) ? (sA + r * 256) : (sBh + (r - 32) * 256);
        float v[8], s = 0.f, s2 = 0.f;
        #pragma unroll
        for (int j = 0; j < 8; j++) {
            v[j] = hr[lane + 32 * j];
            s += v[j]; s2 = fmaf(v[j], v[j], s2);
        }
        #pragma unroll
        for (int o = 16; o; o >>= 1) {
            s  += __shfl_xor_sync(0xffffffffu, s,  o);
            s2 += __shfl_xor_sync(0xffffffffu, s2, o);
        }
        float mu  = s * (1.f / 256.f);
        float var = s2 * (1.f / 256.f) - mu * mu;
        float rstd = rsqrtf(var + 1e-5f);
        #pragma unroll
        for (int j = 0; j < 8; j++) {
            int c = lane + 32 * j;
            float t = (v[j] - mu) * rstd * s_g2[c] + s_be2[c];
            hr[c] = gelu_exact(t);
        }
    }
    __syncthreads();

    // GEMM2: out_pt = h @ w4 + b4 (k = 256 in 8 chunks of 32)
    {
        float4 b0 = *(const float4*)&s_b4[lane * 4];
        float4 b1v = *(const float4*)&s_b4[128 + lane * 4];
        #pragma unroll
        for (int i = 0; i < 8; i++) {
            acc[i][0] = b0.x; acc[i][1] = b0.y; acc[i][2] = b0.z; acc[i][3] = b0.w;
            acc[i][4] = b1v.x; acc[i][5] = b1v.y; acc[i][6] = b1v.z; acc[i][7] = b1v.w;
        }
    }
    for (int kc = 0; kc < 8; kc++) {
        __syncthreads();
        for (int i = tid; i < 2048; i += 256)
            ((float4*)sW)[i] = ((const float4*)(w4 + (size_t)(kc * 32) * 256))[i];
        __syncthreads();
        #pragma unroll 8
        for (int k = 0; k < 32; k++) {
            float4 w0 = *(const float4*)&sW[k * 256 + lane * 4];
            float4 w1v = *(const float4*)&sW[k * 256 + 128 + lane * 4];
            #pragma unroll
            for (int i = 0; i < 8; i++) {
                float a = hb[i][kc * 32 + k];
                acc[i][0] = fmaf(a, w0.x, acc[i][0]);
                acc[i][1] = fmaf(a, w0.y, acc[i][1]);
                acc[i][2] = fmaf(a, w0.z, acc[i][2]);
                acc[i][3] = fmaf(a, w0.w, acc[i][3]);
                acc[i][4] = fmaf(a, w1v.x, acc[i][4]);
                acc[i][5] = fmaf(a, w1v.y, acc[i][5]);
                acc[i][6] = fmaf(a, w1v.z, acc[i][6]);
                acc[i][7] = fmaf(a, w1v.w, acc[i][7]);
            }
        }
    }

    // scatter-max into output
    #pragma unroll
    for (int i = 0; i < 8; i++) {
        int r = warp * 8 + i;
        int ci = s_idx[r];
        int* ob = (int*)(out + ((size_t)b * CC + ci) * 256);
        #pragma unroll
        for (int j = 0; j < 4; j++) {
            float v = acc[i][j];
            if (v > 0.f) atomicMax(ob + lane * 4 + j, __float_as_int(v));
        }
        #pragma unroll
        for (int j = 0; j < 4; j++) {
            float v = acc[i][4 + j];
            if (v > 0.f) atomicMax(ob + 128 + lane * 4 + j, __float_as_int(v));
        }
    }
}

// ---------------------------------------------------------------------------
extern "C" void kernel_launch(void* const* d_in, const int* in_sizes, int n_in,
                              void* d_out, int out_size)
{
    const float* patches = (const float*)d_in[0];
    const void*  nn      = d_in[1];
    // d_in[2] = center_number (scalar) — unused, C hardcoded 1024
    const float* w1  = (const float*)d_in[3];
    const float* b1  = (const float*)d_in[4];
    const float* g1  = (const float*)d_in[5];
    const float* be1 = (const float*)d_in[6];
    const float* w2  = (const float*)d_in[7];
    const float* b2  = (const float*)d_in[8];
    const float* w3  = (const float*)d_in[9];
    const float* b3  = (const float*)d_in[10];
    const float* g2  = (const float*)d_in[11];
    const float* be2 = (const float*)d_in[12];
    const float* w4  = (const float*)d_in[13];
    const float* b4  = (const float*)d_in[14];
    float* out = (float*)d_out;

    cudaFuncSetAttribute(k_conv1,  cudaFuncAttributeMaxDynamicSharedMemorySize, K1_SMEM);
    cudaFuncSetAttribute(k_center, cudaFuncAttributeMaxDynamicSharedMemorySize, KZ_SMEM);
    cudaFuncSetAttribute(k_conv2,  cudaFuncAttributeMaxDynamicSharedMemorySize, K2_SMEM);

    k_detect<<<1, 32>>>(nn);
    k_zero<<<512, 256>>>(out);
    k_conv1<<<BN / TP, 256, K1_SMEM>>>(patches, nn, w1, b1, g1, be1, w2, b2);
    k_center<<<BB * CC / 64, 256, KZ_SMEM>>>(w3, b3);
    k_conv2<<<BN / TP, 256, K2_SMEM>>>(nn, w3, g2, be2, w4, b4, out);
}

// round 7
// speedup vs baseline: 1.3217x; 1.3217x over previous
#include <cuda_runtime.h>
#include <cuda_bf16.h>
#include <math.h>
#include <stdint.h>

// Problem constants
#define BB 8
#define NN 65536
#define CC 1024
#define BN (BB*NN)       // 524288 points
#define NT (BN/128)      // 4096 tiles of 128 points

// smem row strides (bytes): [rows][K+8] bf16 padding -> conflict-free ldmatrix
#define A_STR  272       // K=128 panels: 136 bf16
#define A2_STR 528       // K=256 panels: 264 bf16

// ---------------------------------------------------------------------------
// Device scratch (allocation-free rule)
// ---------------------------------------------------------------------------
__device__ __align__(16) uint32_t g_x1h[(size_t)BN * 64];   // x1 bf16-hi, packed col pairs
__device__ __align__(16) uint32_t g_x1l[(size_t)BN * 64];   // x1 bf16-lo
__device__ __align__(16) float g_y1[(size_t)BB * CC * 128]; // 4 MB
__device__ __align__(16) float g_z [(size_t)BB * CC * 256]; // 8 MB
// dense row-major bf16 hi/lo weights ([k][n], no transpose needed)
__device__ __align__(16) __nv_bfloat16 g_w2h[16384],  g_w2l[16384];   // w2  [128][128]
__device__ __align__(16) __nv_bfloat16 g_w3bh[32768], g_w3bl[32768];  // w3[128:,:] [128][256]
__device__ __align__(16) __nv_bfloat16 g_w4h[65536],  g_w4l[65536];   // w4  [256][256]
__device__ int g_idx64;

// ---------------------------------------------------------------------------
// helpers
// ---------------------------------------------------------------------------
__device__ __forceinline__ uint32_t smem_u32(const void* p)
{
    uint32_t a;
    asm("{ .reg .u64 t; cvta.to.shared.u64 t, %1; cvt.u32.u64 %0, t; }" : "=r"(a) : "l"(p));
    return a;
}
__device__ __forceinline__ void ldmA(uint32_t* r, uint32_t addr)
{
    asm volatile("ldmatrix.sync.aligned.m8n8.x4.shared.b16 {%0,%1,%2,%3}, [%4];"
                 : "=r"(r[0]), "=r"(r[1]), "=r"(r[2]), "=r"(r[3]) : "r"(addr));
}
__device__ __forceinline__ void ldmBT(uint32_t* r, uint32_t addr)
{
    asm volatile("ldmatrix.sync.aligned.m8n8.x4.trans.shared.b16 {%0,%1,%2,%3}, [%4];"
                 : "=r"(r[0]), "=r"(r[1]), "=r"(r[2]), "=r"(r[3]) : "r"(addr));
}
__device__ __forceinline__ void mma16816(float* c, const uint32_t* a, uint32_t b0, uint32_t b1)
{
    asm volatile("mma.sync.aligned.m16n8k16.row.col.f32.bf16.bf16.f32 "
                 "{%0,%1,%2,%3}, {%4,%5,%6,%7}, {%8,%9}, {%0,%1,%2,%3};"
                 : "+f"(c[0]), "+f"(c[1]), "+f"(c[2]), "+f"(c[3])
                 : "r"(a[0]), "r"(a[1]), "r"(a[2]), "r"(a[3]), "r"(b0), "r"(b1));
}
__device__ __forceinline__ void bsplit(float a, float b, uint32_t& ph, uint32_t& pl)
{
    __nv_bfloat16 h0 = __float2bfloat16(a), h1 = __float2bfloat16(b);
    float r0 = a - __bfloat162float(h0), r1 = b - __bfloat162float(h1);
    __nv_bfloat16 l0 = __float2bfloat16(r0), l1 = __float2bfloat16(r1);
    ph = (uint32_t)__bfloat16_as_ushort(h0) | ((uint32_t)__bfloat16_as_ushort(h1) << 16);
    pl = (uint32_t)__bfloat16_as_ushort(l0) | ((uint32_t)__bfloat16_as_ushort(l1) << 16);
}
__device__ __forceinline__ float2 upk2(uint32_t h, uint32_t l)
{
    float2 r;
    r.x = __bfloat162float(__ushort_as_bfloat16((unsigned short)(h & 0xffff)))
        + __bfloat162float(__ushort_as_bfloat16((unsigned short)(l & 0xffff)));
    r.y = __bfloat162float(__ushort_as_bfloat16((unsigned short)(h >> 16)))
        + __bfloat162float(__ushort_as_bfloat16((unsigned short)(l >> 16)));
    return r;
}
__device__ __forceinline__ float gelu_exact(float t)
{
    return 0.5f * t * (1.f + erff(t * 0.70710678118654752f));
}

// ---------------------------------------------------------------------------
// nn_idx dtype detection
// ---------------------------------------------------------------------------
__global__ void k_detect(const void* nn)
{
    if (threadIdx.x == 0 && blockIdx.x == 0) {
        const int* p = (const int*)nn;
        int allzero = 1;
        #pragma unroll 1
        for (int s = 0; s < 64; s++) {
            int i = (int)(((long long)s * 4099) % (BN / 2));
            if (p[2 * i + 1] != 0) { allzero = 0; break; }
        }
        g_idx64 = allzero;
    }
}
__device__ __forceinline__ int load_idx(const void* nn, int i)
{
    if (g_idx64) return (int)((const long long*)nn)[i];
    return ((const int*)nn)[i];
}

// ---------------------------------------------------------------------------
// Zero init
// ---------------------------------------------------------------------------
__global__ void k_zero(float* __restrict__ out)
{
    int i = blockIdx.x * blockDim.x + threadIdx.x;
    int stride = gridDim.x * blockDim.x;
    float4 z = make_float4(0.f, 0.f, 0.f, 0.f);
    const int n_out = BB * CC * 256 / 4;
    for (int j = i; j < n_out; j += stride) ((float4*)out)[j] = z;
    const int n_y = BB * CC * 128 / 4;
    for (int j = i; j < n_y; j += stride) ((float4*)g_y1)[j] = z;
}

// ---------------------------------------------------------------------------
// Weight prep: dense bf16 hi/lo
// ---------------------------------------------------------------------------
__global__ void k_prep(const float* __restrict__ w2, const float* __restrict__ w3,
                       const float* __restrict__ w4)
{
    int idx = blockIdx.x * 256 + threadIdx.x;
    float v; int o;
    __nv_bfloat16 *dh, *dl;
    if (idx < 16384) {
        v = w2[idx]; o = idx; dh = g_w2h; dl = g_w2l;
    } else if (idx < 49152) {
        int e = idx - 16384; v = w3[32768 + e]; o = e; dh = g_w3bh; dl = g_w3bl;
    } else if (idx < 114688) {
        int e = idx - 49152; v = w4[e]; o = e; dh = g_w4h; dl = g_w4l;
    } else return;
    __nv_bfloat16 h = __float2bfloat16(v);
    __nv_bfloat16 l = __float2bfloat16(v - __bfloat162float(h));
    dh[o] = h; dl[o] = l;
}

// ---------------------------------------------------------------------------
// K1: conv1, 128 pts/tile. SIMT layer1+LN+GELU, HMMA GEMM x1 = h@w2 + b2
// ---------------------------------------------------------------------------
#define K1_SMEM 214528
__global__ void __launch_bounds__(256, 1) k_conv1(
    const float* __restrict__ patches, const void* __restrict__ nn,
    const float* __restrict__ w1, const float* __restrict__ b1,
    const float* __restrict__ g1, const float* __restrict__ be1,
    const float* __restrict__ b2)
{
    extern __shared__ __align__(16) unsigned char smr[];
    float* s_a = (float*)smr;                          // [128][128] f32  65536
    unsigned char* sAh = smr + 65536;                  // [128][136] bf16 34816
    unsigned char* sAl = smr + 100352;
    unsigned char* sWh = smr + 135168;
    unsigned char* sWl = smr + 169984;
    float* s_p   = (float*)(smr + 204800);             // 128x8
    float* s_w1  = (float*)(smr + 208896);             // 6x128
    float* s_b1  = (float*)(smr + 211968);
    float* s_g1  = (float*)(smr + 212480);
    float* s_be1 = (float*)(smr + 212992);
    float* s_b2  = (float*)(smr + 213504);
    int*   s_idx = (int*)(smr + 214016);

    const int tid = threadIdx.x;
    const int w = tid >> 5, lane = tid & 31;
    const int tile = blockIdx.x;
    const int p0 = tile * 128;
    const int b = p0 >> 16;

    // copy w2 hi/lo into padded smem
    for (int i = tid; i < 4096; i += 256) {
        int half = i >> 11, row = (i >> 4) & 127, q = i & 15;
        uint4 v = *(const uint4*)((const unsigned char*)(half ? (const void*)g_w2l
                                                              : (const void*)g_w2h) + row * 256 + q * 16);
        *(uint4*)((half ? sWl : sWh) + row * A_STR + q * 16) = v;
    }
    for (int i = tid; i < 768; i += 256) s_w1[i] = w1[i];
    if (tid < 128) {
        s_b1[tid] = b1[tid]; s_g1[tid] = g1[tid];
        s_be1[tid] = be1[tid]; s_b2[tid] = b2[tid];
        s_idx[tid] = load_idx(nn, p0 + tid);
    }
    for (int i = tid; i < 128 * 6; i += 256) {
        int r = i / 6, c = i % 6;
        s_p[r * 8 + c] = patches[(size_t)(p0 + r) * 6 + c];
    }
    __syncthreads();

    // layer1: h = p @ w1 + b1
    for (int e = tid; e < 128 * 128; e += 256) {
        int r = e >> 7, c = e & 127;
        float acc = s_b1[c];
        #pragma unroll
        for (int k = 0; k < 6; k++) acc = fmaf(s_p[r * 8 + k], s_w1[k * 128 + c], acc);
        s_a[e] = acc;
    }
    __syncthreads();

    // LN(128) + GELU
    for (int rl = 0; rl < 16; rl++) {
        int r = w * 16 + rl;
        float v[4], s = 0.f, s2 = 0.f;
        #pragma unroll
        for (int j = 0; j < 4; j++) {
            v[j] = s_a[r * 128 + lane + 32 * j];
            s += v[j]; s2 = fmaf(v[j], v[j], s2);
        }
        #pragma unroll
        for (int o = 16; o; o >>= 1) {
            s  += __shfl_xor_sync(0xffffffffu, s,  o);
            s2 += __shfl_xor_sync(0xffffffffu, s2, o);
        }
        float mu = s * (1.f / 128.f);
        float var = s2 * (1.f / 128.f) - mu * mu;
        float rstd = rsqrtf(var + 1e-5f);
        #pragma unroll
        for (int j = 0; j < 4; j++) {
            int c = lane + 32 * j;
            s_a[r * 128 + c] = gelu_exact((v[j] - mu) * rstd * s_g1[c] + s_be1[c]);
        }
    }
    __syncthreads();

    // bsplit A -> bf16 hi/lo padded panels
    for (int i = tid; i < 8192; i += 256) {
        int row = i >> 6, cp = i & 63;
        uint32_t ph, pl;
        bsplit(s_a[row * 128 + 2 * cp], s_a[row * 128 + 2 * cp + 1], ph, pl);
        *(uint32_t*)(sAh + row * A_STR + cp * 4) = ph;
        *(uint32_t*)(sAl + row * A_STR + cp * 4) = pl;
    }
    __syncthreads();

    // HMMA: D[128x128] = A @ w2 (3-term split). warp grid 4m x 2n, warp tile 32x64
    const int wm = w >> 1, wn = w & 1;
    const uint32_t rA = (lane & 15), kO = (lane >> 4) * 16, nO = (lane >> 4) * 8;
    float acc[2][8][4];
    #pragma unroll
    for (int i = 0; i < 2; i++)
        #pragma unroll
        for (int j = 0; j < 8; j++)
            #pragma unroll
            for (int q = 0; q < 4; q++) acc[i][j][q] = 0.f;

    const uint32_t sAh_b = smem_u32(sAh), sAl_b = smem_u32(sAl);
    const uint32_t sWh_b = smem_u32(sWh), sWl_b = smem_u32(sWl);
    for (int ks = 0; ks < 8; ks++) {
        uint32_t Ah[2][4], Al[2][4], Bh[8][2], Bl[8][2];
        #pragma unroll
        for (int i = 0; i < 2; i++) {
            uint32_t ro = (32 * wm + 16 * i + rA) * A_STR + ks * 32 + kO;
            ldmA(Ah[i], sAh_b + ro);
            ldmA(Al[i], sAl_b + ro);
        }
        #pragma unroll
        for (int jj = 0; jj < 4; jj++) {
            uint32_t ro = (ks * 16 + rA) * A_STR + (wn * 64 + jj * 16 + nO) * 2;
            ldmBT(&Bh[jj * 2][0], sWh_b + ro);
            ldmBT(&Bl[jj * 2][0], sWl_b + ro);
        }
        #pragma unroll
        for (int i = 0; i < 2; i++)
            #pragma unroll
            for (int j = 0; j < 8; j++) {
                mma16816(acc[i][j], Ah[i], Bh[j][0], Bh[j][1]);
                mma16816(acc[i][j], Ah[i], Bl[j][0], Bl[j][1]);
                mma16816(acc[i][j], Al[i], Bh[j][0], Bh[j][1]);
            }
    }

    // epilogue: +b2, atomicMax g_y1, write g_x1 hi/lo
    #pragma unroll
    for (int i = 0; i < 2; i++) {
        int r0 = 32 * wm + 16 * i + (lane >> 2), r1 = r0 + 8;
        int ci0 = s_idx[r0], ci1 = s_idx[r1];
        int* yb0 = (int*)&g_y1[((size_t)b * CC + ci0) * 128];
        int* yb1 = (int*)&g_y1[((size_t)b * CC + ci1) * 128];
        #pragma unroll
        for (int j = 0; j < 8; j++) {
            int c = 64 * wn + 8 * j + 2 * (lane & 3);
            float v0 = acc[i][j][0] + s_b2[c], v1 = acc[i][j][1] + s_b2[c + 1];
            float v2 = acc[i][j][2] + s_b2[c], v3 = acc[i][j][3] + s_b2[c + 1];
            if (v0 > 0.f) atomicMax(yb0 + c,     __float_as_int(v0));
            if (v1 > 0.f) atomicMax(yb0 + c + 1, __float_as_int(v1));
            if (v2 > 0.f) atomicMax(yb1 + c,     __float_as_int(v2));
            if (v3 > 0.f) atomicMax(yb1 + c + 1, __float_as_int(v3));
            uint32_t ph, pl;
            bsplit(v0, v1, ph, pl);
            g_x1h[(size_t)tile * 8192 + r0 * 64 + (c >> 1)] = ph;
            g_x1l[(size_t)tile * 8192 + r0 * 64 + (c >> 1)] = pl;
            bsplit(v2, v3, ph, pl);
            g_x1h[(size_t)tile * 8192 + r1 * 64 + (c >> 1)] = ph;
            g_x1l[(size_t)tile * 8192 + r1 * 64 + (c >> 1)] = pl;
        }
    }
}

// ---------------------------------------------------------------------------
// Kz: g_z = g_y1 @ w3[0:128,:] + b3  (fp32 SIMT — tiny)
// ---------------------------------------------------------------------------
#define KZ_SMEM (16640 * 4)
__global__ void __launch_bounds__(256, 2) k_center(
    const float* __restrict__ w3, const float* __restrict__ b3)
{
    extern __shared__ __align__(16) float sm[];
    float* s_y  = sm;
    float* s_w  = sm + 8192;
    float* s_b3 = sm + 16384;
    const int tid = threadIdx.x;
    const int bc0 = blockIdx.x * 64;
    for (int i = tid; i < 2048; i += 256)
        ((float4*)s_y)[i] = ((const float4*)(g_y1 + (size_t)bc0 * 128))[i];
    s_b3[tid & 255] = b3[tid & 255];
    const int warp = tid >> 5, lane = tid & 31;
    float acc[8][8];
    #pragma unroll
    for (int i = 0; i < 8; i++)
        #pragma unroll
        for (int j = 0; j < 8; j++) acc[i][j] = 0.f;
    for (int kc = 0; kc < 4; kc++) {
        __syncthreads();
        for (int i = tid; i < 2048; i += 256)
            ((float4*)s_w)[i] = ((const float4*)(w3 + (size_t)(kc * 32) * 256))[i];
        __syncthreads();
        #pragma unroll 8
        for (int k = 0; k < 32; k++) {
            float4 w0 = *(const float4*)&s_w[k * 256 + lane * 4];
            float4 w1v = *(const float4*)&s_w[k * 256 + 128 + lane * 4];
            #pragma unroll
            for (int i = 0; i < 8; i++) {
                float a = s_y[(warp * 8 + i) * 128 + kc * 32 + k];
                acc[i][0] = fmaf(a, w0.x, acc[i][0]);
                acc[i][1] = fmaf(a, w0.y, acc[i][1]);
                acc[i][2] = fmaf(a, w0.z, acc[i][2]);
                acc[i][3] = fmaf(a, w0.w, acc[i][3]);
                acc[i][4] = fmaf(a, w1v.x, acc[i][4]);
                acc[i][5] = fmaf(a, w1v.y, acc[i][5]);
                acc[i][6] = fmaf(a, w1v.z, acc[i][6]);
                acc[i][7] = fmaf(a, w1v.w, acc[i][7]);
            }
        }
    }
    #pragma unroll
    for (int i = 0; i < 8; i++) {
        size_t zo = (size_t)(bc0 + warp * 8 + i) * 256;
        *(float4*)&g_z[zo + lane * 4] = make_float4(
            acc[i][0] + s_b3[lane * 4], acc[i][1] + s_b3[lane * 4 + 1],
            acc[i][2] + s_b3[lane * 4 + 2], acc[i][3] + s_b3[lane * 4 + 3]);
        *(float4*)&g_z[zo + 128 + lane * 4] = make_float4(
            acc[i][4] + s_b3[128 + lane * 4], acc[i][5] + s_b3[128 + lane * 4 + 1],
            acc[i][6] + s_b3[128 + lane * 4 + 2], acc[i][7] + s_b3[128 + lane * 4 + 3]);
    }
}

// ---------------------------------------------------------------------------
// K2: conv2, 128 pts/tile, HMMA both GEMMs.
//   D1 = x1@w3bot (+z gathered) -> stats -> LN+GELU in place -> D2 = h@w4 -> max
// ---------------------------------------------------------------------------
#define K2_SMEM 226816
__global__ void __launch_bounds__(256, 1) k_conv2(
    const void* __restrict__ nn,
    const float* __restrict__ g2, const float* __restrict__ be2,
    const float* __restrict__ b4, float* __restrict__ out)
{
    extern __shared__ __align__(16) unsigned char smr[];
    unsigned char* sAh = smr;                          // [128][136] 34816
    unsigned char* sAl = smr + 34816;
    unsigned char* A2h = smr + 69632;                  // [128][264] 67584
    unsigned char* A2l = smr + 137216;
    unsigned char* sWh = smr + 204800;                 // [32][136]  8704
    unsigned char* sWl = smr + 213504;
    int*   s_idx = (int*)(smr + 222208);
    float* s_g2  = (float*)(smr + 222720);
    float* s_be2 = (float*)(smr + 223744);
    float* s_b4  = (float*)(smr + 224768);
    float* s_sum = (float*)(smr + 225792);
    float* s_sq  = (float*)(smr + 226304);

    const int tid = threadIdx.x;
    const int w = tid >> 5, lane = tid & 31;
    const int tile = blockIdx.x;
    const int p0 = tile * 128;
    const int b = p0 >> 16;

    // copy A1 (x1 hi/lo) into padded smem
    for (int i = tid; i < 4096; i += 256) {
        int half = i >> 11, row = (i >> 4) & 127, q = i & 15;
        uint4 v = ((const uint4*)((half ? g_x1l : g_x1h) + (size_t)tile * 8192))[row * 16 + q];
        *(uint4*)((half ? sAl : sAh) + row * A_STR + q * 16) = v;
    }
    if (tid < 128) { s_idx[tid] = load_idx(nn, p0 + tid); s_sum[tid] = 0.f; s_sq[tid] = 0.f; }
    s_g2[tid] = g2[tid]; s_be2[tid] = be2[tid]; s_b4[tid] = b4[tid];
    __syncthreads();

    const int wm = w >> 1, wn = w & 1;
    const uint32_t rA = (lane & 15), kO = (lane >> 4) * 16, nO = (lane >> 4) * 8;
    const uint32_t sAh_b = smem_u32(sAh), sAl_b = smem_u32(sAl);
    const uint32_t A2h_b = smem_u32(A2h), A2l_b = smem_u32(A2l);
    const uint32_t sWh_b = smem_u32(sWh), sWl_b = smem_u32(sWl);

    // row/ci/z bases for this thread's 4 fragment rows
    int rr[4];
    rr[0] = 32 * wm + (lane >> 2); rr[1] = rr[0] + 8; rr[2] = rr[0] + 16; rr[3] = rr[0] + 24;
    const float* zb[4];
    #pragma unroll
    for (int q = 0; q < 4; q++) zb[q] = g_z + ((size_t)b * CC + s_idx[rr[q]]) * 256;

    // ---- GEMM1: D1 = x1 @ w3bot, two N-halves ----
    for (int nh = 0; nh < 2; nh++) {
        float acc[2][8][4];
        #pragma unroll
        for (int i = 0; i < 2; i++)
            #pragma unroll
            for (int j = 0; j < 8; j++)
                #pragma unroll
                for (int q = 0; q < 4; q++) acc[i][j][q] = 0.f;

        for (int kc = 0; kc < 4; kc++) {
            __syncthreads();
            for (int i = tid; i < 1024; i += 256) {
                int half = i >> 9, row = (i >> 4) & 31, q = i & 15;
                uint4 v = *(const uint4*)((const unsigned char*)(half ? (const void*)g_w3bl
                          : (const void*)g_w3bh) + (kc * 32 + row) * 512 + nh * 256 + q * 16);
                *(uint4*)((half ? sWl : sWh) + row * A_STR + q * 16) = v;
            }
            __syncthreads();
            for (int ks2 = 0; ks2 < 2; ks2++) {
                int ks = kc * 2 + ks2;
                uint32_t Ah[2][4], Al[2][4], Bh[8][2], Bl[8][2];
                #pragma unroll
                for (int i = 0; i < 2; i++) {
                    uint32_t ro = (32 * wm + 16 * i + rA) * A_STR + ks * 32 + kO;
                    ldmA(Ah[i], sAh_b + ro);
                    ldmA(Al[i], sAl_b + ro);
                }
                #pragma unroll
                for (int jj = 0; jj < 4; jj++) {
                    uint32_t ro = (ks2 * 16 + rA) * A_STR + (wn * 64 + jj * 16 + nO) * 2;
                    ldmBT(&Bh[jj * 2][0], sWh_b + ro);
                    ldmBT(&Bl[jj * 2][0], sWl_b + ro);
                }
                #pragma unroll
                for (int i = 0; i < 2; i++)
                    #pragma unroll
                    for (int j = 0; j < 8; j++) {
                        mma16816(acc[i][j], Ah[i], Bh[j][0], Bh[j][1]);
                        mma16816(acc[i][j], Ah[i], Bl[j][0], Bl[j][1]);
                        mma16816(acc[i][j], Al[i], Bh[j][0], Bh[j][1]);
                    }
            }
        }

        // store acc + z into A2 (pre-LN, bf16 hi/lo) + accumulate stats
        float sums[4] = {0.f, 0.f, 0.f, 0.f}, sqs[4] = {0.f, 0.f, 0.f, 0.f};
        #pragma unroll
        for (int i = 0; i < 2; i++)
            #pragma unroll
            for (int j = 0; j < 8; j++) {
                int c = nh * 128 + 64 * wn + 8 * j + 2 * (lane & 3);
                int q0 = i * 2, q1 = i * 2 + 1;
                float2 z0 = *(const float2*)(zb[q0] + c);
                float2 z1 = *(const float2*)(zb[q1] + c);
                float v0 = acc[i][j][0] + z0.x, v1 = acc[i][j][1] + z0.y;
                float v2 = acc[i][j][2] + z1.x, v3 = acc[i][j][3] + z1.y;
                sums[q0] += v0 + v1; sqs[q0] = fmaf(v0, v0, fmaf(v1, v1, sqs[q0]));
                sums[q1] += v2 + v3; sqs[q1] = fmaf(v2, v2, fmaf(v3, v3, sqs[q1]));
                uint32_t ph, pl;
                bsplit(v0, v1, ph, pl);
                *(uint32_t*)(A2h + rr[q0] * A2_STR + c * 2) = ph;
                *(uint32_t*)(A2l + rr[q0] * A2_STR + c * 2) = pl;
                bsplit(v2, v3, ph, pl);
                *(uint32_t*)(A2h + rr[q1] * A2_STR + c * 2) = ph;
                *(uint32_t*)(A2l + rr[q1] * A2_STR + c * 2) = pl;
            }
        #pragma unroll
        for (int o = 1; o <= 2; o <<= 1)
            #pragma unroll
            for (int q = 0; q < 4; q++) {
                sums[q] += __shfl_xor_sync(0xffffffffu, sums[q], o);
                sqs[q]  += __shfl_xor_sync(0xffffffffu, sqs[q],  o);
            }
        if ((lane & 3) == 0)
            #pragma unroll
            for (int q = 0; q < 4; q++) {
                atomicAdd(&s_sum[rr[q]], sums[q]);
                atomicAdd(&s_sq[rr[q]],  sqs[q]);
            }
    }
    __syncthreads();

    // ---- LN + GELU in place on A2 (warp w owns rows 16w..16w+15) ----
    for (int rl = 0; rl < 16; rl++) {
        int r = w * 16 + rl;
        float mu = s_sum[r] * (1.f / 256.f);
        float var = s_sq[r] * (1.f / 256.f) - mu * mu;
        float rstd = rsqrtf(var + 1e-5f);
        uint4* ph4 = (uint4*)(A2h + r * A2_STR + lane * 16);
        uint4* pl4 = (uint4*)(A2l + r * A2_STR + lane * 16);
        uint4 h4 = *ph4, l4 = *pl4;
        const uint32_t* hw = &h4.x;
        const uint32_t* lw = &l4.x;
        uint4 nh4, nl4;
        uint32_t* nhw = &nh4.x;
        uint32_t* nlw = &nl4.x;
        int c0 = lane * 8;
        #pragma unroll
        for (int p = 0; p < 4; p++) {
            float2 v = upk2(hw[p], lw[p]);
            int c = c0 + 2 * p;
            float t0 = gelu_exact((v.x - mu) * rstd * s_g2[c] + s_be2[c]);
            float t1 = gelu_exact((v.y - mu) * rstd * s_g2[c + 1] + s_be2[c + 1]);
            bsplit(t0, t1, nhw[p], nlw[p]);
        }
        *ph4 = nh4; *pl4 = nl4;
    }
    __syncthreads();

    // ---- GEMM2: D2 = h @ w4, two N-halves, K=256 streamed ----
    for (int nh = 0; nh < 2; nh++) {
        float acc[2][8][4];
        #pragma unroll
        for (int i = 0; i < 2; i++)
            #pragma unroll
            for (int j = 0; j < 8; j++)
                #pragma unroll
                for (int q = 0; q < 4; q++) acc[i][j][q] = 0.f;

        for (int kc = 0; kc < 8; kc++) {
            __syncthreads();
            for (int i = tid; i < 1024; i += 256) {
                int half = i >> 9, row = (i >> 4) & 31, q = i & 15;
                uint4 v = *(const uint4*)((const unsigned char*)(half ? (const void*)g_w4l
                          : (const void*)g_w4h) + (kc * 32 + row) * 512 + nh * 256 + q * 16);
                *(uint4*)((half ? sWl : sWh) + row * A_STR + q * 16) = v;
            }
            __syncthreads();
            for (int ks2 = 0; ks2 < 2; ks2++) {
                int ks = kc * 2 + ks2;
                uint32_t Ah[2][4], Al[2][4], Bh[8][2], Bl[8][2];
                #pragma unroll
                for (int i = 0; i < 2; i++) {
                    uint32_t ro = (32 * wm + 16 * i + rA) * A2_STR + ks * 32 + kO;
                    ldmA(Ah[i], A2h_b + ro);
                    ldmA(Al[i], A2l_b + ro);
                }
                #pragma unroll
                for (int jj = 0; jj < 4; jj++) {
                    uint32_t ro = (ks2 * 16 + rA) * A_STR + (wn * 64 + jj * 16 + nO) * 2;
                    ldmBT(&Bh[jj * 2][0], sWh_b + ro);
                    ldmBT(&Bl[jj * 2][0], sWl_b + ro);
                }
                #pragma unroll
                for (int i = 0; i < 2; i++)
                    #pragma unroll
                    for (int j = 0; j < 8; j++) {
                        mma16816(acc[i][j], Ah[i], Bh[j][0], Bh[j][1]);
                        mma16816(acc[i][j], Ah[i], Bl[j][0], Bl[j][1]);
                        mma16816(acc[i][j], Al[i], Bh[j][0], Bh[j][1]);
                    }
            }
        }

        // epilogue: +b4, scatter-max
        #pragma unroll
        for (int i = 0; i < 2; i++) {
            int q0 = i * 2, q1 = i * 2 + 1;
            int* ob0 = (int*)(out + ((size_t)b * CC + s_idx[rr[q0]]) * 256);
            int* ob1 = (int*)(out + ((size_t)b * CC + s_idx[rr[q1]]) * 256);
            #pragma unroll
            for (int j = 0; j < 8; j++) {
                int c = nh * 128 + 64 * wn + 8 * j + 2 * (lane & 3);
                float v0 = acc[i][j][0] + s_b4[c], v1 = acc[i][j][1] + s_b4[c + 1];
                float v2 = acc[i][j][2] + s_b4[c], v3 = acc[i][j][3] + s_b4[c + 1];
                if (v0 > 0.f) atomicMax(ob0 + c,     __float_as_int(v0));
                if (v1 > 0.f) atomicMax(ob0 + c + 1, __float_as_int(v1));
                if (v2 > 0.f) atomicMax(ob1 + c,     __float_as_int(v2));
                if (v3 > 0.f) atomicMax(ob1 + c + 1, __float_as_int(v3));
            }
        }
    }
}

// ---------------------------------------------------------------------------
extern "C" void kernel_launch(void* const* d_in, const int* in_sizes, int n_in,
                              void* d_out, int out_size)
{
    const float* patches = (const float*)d_in[0];
    const void*  nn      = d_in[1];
    const float* w1  = (const float*)d_in[3];
    const float* b1  = (const float*)d_in[4];
    const float* g1  = (const float*)d_in[5];
    const float* be1 = (const float*)d_in[6];
    const float* w2  = (const float*)d_in[7];
    const float* b2  = (const float*)d_in[8];
    const float* w3  = (const float*)d_in[9];
    const float* b3  = (const float*)d_in[10];
    const float* g2  = (const float*)d_in[11];
    const float* be2 = (const float*)d_in[12];
    const float* w4  = (const float*)d_in[13];
    const float* b4  = (const float*)d_in[14];
    float* out = (float*)d_out;

    cudaFuncSetAttribute(k_conv1,  cudaFuncAttributeMaxDynamicSharedMemorySize, K1_SMEM);
    cudaFuncSetAttribute(k_center, cudaFuncAttributeMaxDynamicSharedMemorySize, KZ_SMEM);
    cudaFuncSetAttribute(k_conv2,  cudaFuncAttributeMaxDynamicSharedMemorySize, K2_SMEM);

    k_detect<<<1, 32>>>(nn);
    k_zero<<<512, 256>>>(out);
    k_prep<<<448, 256>>>(w2, w3, w4);
    k_conv1<<<NT, 256, K1_SMEM>>>(patches, nn, w1, b1, g1, be1, b2);
    k_center<<<BB * CC / 64, 256, KZ_SMEM>>>(w3, b3);
    k_conv2<<<NT, 256, K2_SMEM>>>(nn, g2, be2, b4, out);
}

// round 12
// speedup vs baseline: 1.9486x; 1.4743x over previous
#include <cuda_runtime.h>
#include <cuda_bf16.h>
#include <math.h>
#include <stdint.h>

// Problem constants
#define BB 8
#define NN 65536
#define CC 1024
#define BN (BB*NN)       // 524288 points
#define NTB (BN/64)      // 8192 tiles of 64 points

#define A_STR  272       // [rows][128+8] bf16 rows, bytes
#define W_STR  528       // [rows][256+8] bf16 rows, bytes
#define A2_STR 528

// ---------------------------------------------------------------------------
// Device scratch
// ---------------------------------------------------------------------------
__device__ __align__(16) uint32_t g_x1h[(size_t)BN * 64];
__device__ __align__(16) uint32_t g_x1l[(size_t)BN * 64];
__device__ __align__(16) float g_y1[(size_t)BB * CC * 128];
__device__ __align__(16) float g_z [(size_t)BB * CC * 256];
__device__ __align__(16) __nv_bfloat16 g_w2h[16384],  g_w2l[16384];   // w2  [128][128]
__device__ __align__(16) __nv_bfloat16 g_w3bh[32768], g_w3bl[32768];  // w3[128:,:] [128][256]
__device__ __align__(16) __nv_bfloat16 g_w4h[65536],  g_w4l[65536];   // w4  [256][256]
__device__ int g_idx64;

// ---------------------------------------------------------------------------
// helpers
// ---------------------------------------------------------------------------
__device__ __forceinline__ uint32_t smem_u32(const void* p)
{
    uint32_t a;
    asm("{ .reg .u64 t; cvta.to.shared.u64 t, %1; cvt.u32.u64 %0, t; }" : "=r"(a) : "l"(p));
    return a;
}
__device__ __forceinline__ void ldmA(uint32_t* r, uint32_t addr)
{
    asm volatile("ldmatrix.sync.aligned.m8n8.x4.shared.b16 {%0,%1,%2,%3}, [%4];"
                 : "=r"(r[0]), "=r"(r[1]), "=r"(r[2]), "=r"(r[3]) : "r"(addr));
}
__device__ __forceinline__ void ldmBT(uint32_t* r, uint32_t addr)
{
    asm volatile("ldmatrix.sync.aligned.m8n8.x4.trans.shared.b16 {%0,%1,%2,%3}, [%4];"
                 : "=r"(r[0]), "=r"(r[1]), "=r"(r[2]), "=r"(r[3]) : "r"(addr));
}
__device__ __forceinline__ void mma16816(float* c, const uint32_t* a, uint32_t b0, uint32_t b1)
{
    asm volatile("mma.sync.aligned.m16n8k16.row.col.f32.bf16.bf16.f32 "
                 "{%0,%1,%2,%3}, {%4,%5,%6,%7}, {%8,%9}, {%0,%1,%2,%3};"
                 : "+f"(c[0]), "+f"(c[1]), "+f"(c[2]), "+f"(c[3])
                 : "r"(a[0]), "r"(a[1]), "r"(a[2]), "r"(a[3]), "r"(b0), "r"(b1));
}
__device__ __forceinline__ void bsplit(float a, float b, uint32_t& ph, uint32_t& pl)
{
    __nv_bfloat16 h0 = __float2bfloat16(a), h1 = __float2bfloat16(b);
    float r0 = a - __bfloat162float(h0), r1 = b - __bfloat162float(h1);
    __nv_bfloat16 l0 = __float2bfloat16(r0), l1 = __float2bfloat16(r1);
    ph = (uint32_t)__bfloat16_as_ushort(h0) | ((uint32_t)__bfloat16_as_ushort(h1) << 16);
    pl = (uint32_t)__bfloat16_as_ushort(l0) | ((uint32_t)__bfloat16_as_ushort(l1) << 16);
}
__device__ __forceinline__ float2 upk2(uint32_t h, uint32_t l)
{
    float2 r;
    r.x = __bfloat162float(__ushort_as_bfloat16((unsigned short)(h & 0xffff)))
        + __bfloat162float(__ushort_as_bfloat16((unsigned short)(l & 0xffff)));
    r.y = __bfloat162float(__ushort_as_bfloat16((unsigned short)(h >> 16)))
        + __bfloat162float(__ushort_as_bfloat16((unsigned short)(l >> 16)));
    return r;
}
__device__ __forceinline__ float gelu_exact(float t)
{
    return 0.5f * t * (1.f + erff(t * 0.70710678118654752f));
}

// ---------------------------------------------------------------------------
__global__ void k_detect(const void* nn)
{
    if (threadIdx.x == 0 && blockIdx.x == 0) {
        const int* p = (const int*)nn;
        int allzero = 1;
        #pragma unroll 1
        for (int s = 0; s < 64; s++) {
            int i = (int)(((long long)s * 4099) % (BN / 2));
            if (p[2 * i + 1] != 0) { allzero = 0; break; }
        }
        g_idx64 = allzero;
    }
}
__device__ __forceinline__ int load_idx(const void* nn, int i)
{
    if (g_idx64) return (int)((const long long*)nn)[i];
    return ((const int*)nn)[i];
}

__global__ void k_zero(float* __restrict__ out)
{
    int i = blockIdx.x * blockDim.x + threadIdx.x;
    int stride = gridDim.x * blockDim.x;
    float4 z = make_float4(0.f, 0.f, 0.f, 0.f);
    const int n_out = BB * CC * 256 / 4;
    for (int j = i; j < n_out; j += stride) ((float4*)out)[j] = z;
    const int n_y = BB * CC * 128 / 4;
    for (int j = i; j < n_y; j += stride) ((float4*)g_y1)[j] = z;
}

__global__ void k_prep(const float* __restrict__ w2, const float* __restrict__ w3,
                       const float* __restrict__ w4)
{
    int idx = blockIdx.x * 256 + threadIdx.x;
    float v; int o;
    __nv_bfloat16 *dh, *dl;
    if (idx < 16384) {
        v = w2[idx]; o = idx; dh = g_w2h; dl = g_w2l;
    } else if (idx < 49152) {
        int e = idx - 16384; v = w3[32768 + e]; o = e; dh = g_w3bh; dl = g_w3bl;
    } else if (idx < 114688) {
        int e = idx - 49152; v = w4[e]; o = e; dh = g_w4h; dl = g_w4l;
    } else return;
    __nv_bfloat16 h = __float2bfloat16(v);
    __nv_bfloat16 l = __float2bfloat16(v - __bfloat162float(h));
    dh[o] = h; dl[o] = l;
}

// ---------------------------------------------------------------------------
// K1: conv1, 64 pts/tile, occupancy 2. Fused reg-resident layer1+LN+GELU,
//     HMMA x1 = h @ w2 + b2 -> g_x1 panels + atomicMax g_y1
// ---------------------------------------------------------------------------
#define K1_SMEM 111872
__global__ void __launch_bounds__(256, 2) k_conv1(
    const float* __restrict__ patches, const void* __restrict__ nn,
    const float* __restrict__ w1, const float* __restrict__ b1,
    const float* __restrict__ g1, const float* __restrict__ be1,
    const float* __restrict__ b2)
{
    extern __shared__ __align__(16) unsigned char smr[];
    unsigned char* sAh = smr;               // [64][136]bf16  17408
    unsigned char* sAl = smr + 17408;
    unsigned char* sWh = smr + 34816;       // [128][136]bf16 34816
    unsigned char* sWl = smr + 69632;
    float* s_p   = (float*)(smr + 104448);  // 64x8
    float* s_w1  = (float*)(smr + 106496);  // 6x128
    float* s_b1  = (float*)(smr + 109568);
    float* s_g1  = (float*)(smr + 110080);
    float* s_be1 = (float*)(smr + 110592);
    float* s_b2  = (float*)(smr + 111104);
    int*   s_idx = (int*)(smr + 111616);

    const int tid = threadIdx.x;
    const int w = tid >> 5, lane = tid & 31;
    const int p0 = blockIdx.x * 64;
    const int b = p0 >> 16;

    for (int i = tid; i < 4096; i += 256) {
        int half = i >> 11, row = (i >> 4) & 127, q = i & 15;
        uint4 v = *(const uint4*)((const unsigned char*)(half ? (const void*)g_w2l
                                                              : (const void*)g_w2h) + row * 256 + q * 16);
        *(uint4*)((half ? sWl : sWh) + row * A_STR + q * 16) = v;
    }
    for (int i = tid; i < 768; i += 256) s_w1[i] = w1[i];
    if (tid < 128) {
        s_b1[tid] = b1[tid]; s_g1[tid] = g1[tid];
        s_be1[tid] = be1[tid]; s_b2[tid] = b2[tid];
    }
    if (tid < 64) s_idx[tid] = load_idx(nn, p0 + tid);
    for (int i = tid; i < 384; i += 256) {
        int r = i / 6, c = i % 6;
        s_p[r * 8 + c] = patches[(size_t)(p0 + r) * 6 + c];
    }
    __syncthreads();

    // fused layer1 + LN(128) + GELU + bsplit -> panels. warp w: rows 8w..8w+7
    for (int rl = 0; rl < 8; rl++) {
        int r = w * 8 + rl;
        float pv[6];
        #pragma unroll
        for (int k = 0; k < 6; k++) pv[k] = s_p[r * 8 + k];
        float v[4], s = 0.f, s2 = 0.f;
        #pragma unroll
        for (int j = 0; j < 4; j++) {
            int c = 4 * lane + j;
            float a = s_b1[c];
            #pragma unroll
            for (int k = 0; k < 6; k++) a = fmaf(pv[k], s_w1[k * 128 + c], a);
            v[j] = a; s += a; s2 = fmaf(a, a, s2);
        }
        #pragma unroll
        for (int o = 16; o; o >>= 1) {
            s  += __shfl_xor_sync(0xffffffffu, s,  o);
            s2 += __shfl_xor_sync(0xffffffffu, s2, o);
        }
        float mu = s * (1.f / 128.f);
        float var = s2 * (1.f / 128.f) - mu * mu;
        float rstd = rsqrtf(var + 1e-5f);
        float t[4];
        #pragma unroll
        for (int j = 0; j < 4; j++) {
            int c = 4 * lane + j;
            t[j] = gelu_exact((v[j] - mu) * rstd * s_g1[c] + s_be1[c]);
        }
        uint32_t ph, pl;
        bsplit(t[0], t[1], ph, pl);
        *(uint32_t*)(sAh + r * A_STR + lane * 8) = ph;
        *(uint32_t*)(sAl + r * A_STR + lane * 8) = pl;
        bsplit(t[2], t[3], ph, pl);
        *(uint32_t*)(sAh + r * A_STR + lane * 8 + 4) = ph;
        *(uint32_t*)(sAl + r * A_STR + lane * 8 + 4) = pl;
    }
    __syncthreads();

    // HMMA: D[64x128] = A @ w2 (3-term split). warp: rows 16wm.., cols 64wn..
    const int wm = w >> 1, wn = w & 1;
    const uint32_t rA = (lane & 15), kO = (lane >> 4) * 16, nO = (lane >> 4) * 8;
    const uint32_t sAh_b = smem_u32(sAh), sAl_b = smem_u32(sAl);
    const uint32_t sWh_b = smem_u32(sWh), sWl_b = smem_u32(sWl);
    float acc[8][4];
    #pragma unroll
    for (int f = 0; f < 8; f++)
        #pragma unroll
        for (int q = 0; q < 4; q++) acc[f][q] = 0.f;

    for (int ks = 0; ks < 8; ks++) {
        uint32_t Ah[4], Al[4];
        uint32_t ro = (16 * wm + rA) * A_STR + ks * 32 + kO;
        ldmA(Ah, sAh_b + ro);
        ldmA(Al, sAl_b + ro);
        #pragma unroll
        for (int g = 0; g < 2; g++) {
            uint32_t Bh[4][2], Bl[4][2];
            #pragma unroll
            for (int jj = 0; jj < 2; jj++) {
                uint32_t ro2 = (ks * 16 + rA) * A_STR + (64 * wn + 32 * g + jj * 16 + nO) * 2;
                ldmBT(&Bh[jj * 2][0], sWh_b + ro2);
                ldmBT(&Bl[jj * 2][0], sWl_b + ro2);
            }
            #pragma unroll
            for (int f = 0; f < 4; f++) {
                mma16816(acc[4 * g + f], Ah, Bh[f][0], Bh[f][1]);
                mma16816(acc[4 * g + f], Ah, Bl[f][0], Bl[f][1]);
                mma16816(acc[4 * g + f], Al, Bh[f][0], Bh[f][1]);
            }
        }
    }

    // epilogue
    {
        int r0 = 16 * wm + (lane >> 2), r1 = r0 + 8;
        int* yb0 = (int*)&g_y1[((size_t)b * CC + s_idx[r0]) * 128];
        int* yb1 = (int*)&g_y1[((size_t)b * CC + s_idx[r1]) * 128];
        #pragma unroll
        for (int f = 0; f < 8; f++) {
            int c = 64 * wn + 8 * f + 2 * (lane & 3);
            float v0 = acc[f][0] + s_b2[c], v1 = acc[f][1] + s_b2[c + 1];
            float v2 = acc[f][2] + s_b2[c], v3 = acc[f][3] + s_b2[c + 1];
            if (v0 > 0.f) atomicMax(yb0 + c,     __float_as_int(v0));
            if (v1 > 0.f) atomicMax(yb0 + c + 1, __float_as_int(v1));
            if (v2 > 0.f) atomicMax(yb1 + c,     __float_as_int(v2));
            if (v3 > 0.f) atomicMax(yb1 + c + 1, __float_as_int(v3));
            uint32_t ph, pl;
            bsplit(v0, v1, ph, pl);
            g_x1h[(size_t)(p0 + r0) * 64 + (c >> 1)] = ph;
            g_x1l[(size_t)(p0 + r0) * 64 + (c >> 1)] = pl;
            bsplit(v2, v3, ph, pl);
            g_x1h[(size_t)(p0 + r1) * 64 + (c >> 1)] = ph;
            g_x1l[(size_t)(p0 + r1) * 64 + (c >> 1)] = pl;
        }
    }
}

// ---------------------------------------------------------------------------
// Kz: g_z = g_y1 @ w3[0:128,:] + b3  (fp32 SIMT — tiny)
// ---------------------------------------------------------------------------
#define KZ_SMEM (16640 * 4)
__global__ void __launch_bounds__(256, 2) k_center(
    const float* __restrict__ w3, const float* __restrict__ b3)
{
    extern __shared__ __align__(16) float sm[];
    float* s_y  = sm;
    float* s_w  = sm + 8192;
    float* s_b3 = sm + 16384;
    const int tid = threadIdx.x;
    const int bc0 = blockIdx.x * 64;
    for (int i = tid; i < 2048; i += 256)
        ((float4*)s_y)[i] = ((const float4*)(g_y1 + (size_t)bc0 * 128))[i];
    s_b3[tid & 255] = b3[tid & 255];
    const int warp = tid >> 5, lane = tid & 31;
    float acc[8][8];
    #pragma unroll
    for (int i = 0; i < 8; i++)
        #pragma unroll
        for (int j = 0; j < 8; j++) acc[i][j] = 0.f;
    for (int kc = 0; kc < 4; kc++) {
        __syncthreads();
        for (int i = tid; i < 2048; i += 256)
            ((float4*)s_w)[i] = ((const float4*)(w3 + (size_t)(kc * 32) * 256))[i];
        __syncthreads();
        #pragma unroll 8
        for (int k = 0; k < 32; k++) {
            float4 w0 = *(const float4*)&s_w[k * 256 + lane * 4];
            float4 w1v = *(const float4*)&s_w[k * 256 + 128 + lane * 4];
            #pragma unroll
            for (int i = 0; i < 8; i++) {
                float a = s_y[(warp * 8 + i) * 128 + kc * 32 + k];
                acc[i][0] = fmaf(a, w0.x, acc[i][0]);
                acc[i][1] = fmaf(a, w0.y, acc[i][1]);
                acc[i][2] = fmaf(a, w0.z, acc[i][2]);
                acc[i][3] = fmaf(a, w0.w, acc[i][3]);
                acc[i][4] = fmaf(a, w1v.x, acc[i][4]);
                acc[i][5] = fmaf(a, w1v.y, acc[i][5]);
                acc[i][6] = fmaf(a, w1v.z, acc[i][6]);
                acc[i][7] = fmaf(a, w1v.w, acc[i][7]);
            }
        }
    }
    #pragma unroll
    for (int i = 0; i < 8; i++) {
        size_t zo = (size_t)(bc0 + warp * 8 + i) * 256;
        *(float4*)&g_z[zo + lane * 4] = make_float4(
            acc[i][0] + s_b3[lane * 4], acc[i][1] + s_b3[lane * 4 + 1],
            acc[i][2] + s_b3[lane * 4 + 2], acc[i][3] + s_b3[lane * 4 + 3]);
        *(float4*)&g_z[zo + 128 + lane * 4] = make_float4(
            acc[i][4] + s_b3[128 + lane * 4], acc[i][5] + s_b3[128 + lane * 4 + 1],
            acc[i][6] + s_b3[128 + lane * 4 + 2], acc[i][7] + s_b3[128 + lane * 4 + 3]);
    }
}

// ---------------------------------------------------------------------------
// K2: conv2, 64 pts/tile, occupancy 2. HMMA both GEMMs; A1 aliased inside A2.
// ---------------------------------------------------------------------------
#define K2_SMEM 105216
__global__ void __launch_bounds__(256, 2) k_conv2(
    const void* __restrict__ nn,
    const float* __restrict__ g2, const float* __restrict__ be2,
    const float* __restrict__ b4, float* __restrict__ out)
{
    extern __shared__ __align__(16) unsigned char smr[];
    unsigned char* A2h = smr;               // [64][264]bf16  33792 ; A1h aliased at base (stride 272)
    unsigned char* A2l = smr + 33792;       //                        A1l aliased at base
    unsigned char* sWh = smr + 67584;       // [32][264]bf16  16896
    unsigned char* sWl = smr + 84480;
    int*   s_idx = (int*)(smr + 101376);
    float* s_g2  = (float*)(smr + 101632);
    float* s_be2 = (float*)(smr + 102656);
    float* s_b4  = (float*)(smr + 103680);
    float* s_sum = (float*)(smr + 104704);
    float* s_sq  = (float*)(smr + 104960);

    const int tid = threadIdx.x;
    const int w = tid >> 5, lane = tid & 31;
    const int p0 = blockIdx.x * 64;
    const int b = p0 >> 16;

    // load A1 panels (aliased at A2 bases, stride A_STR)
    for (int i = tid; i < 2048; i += 256) {
        int half = i >> 10, row = (i >> 4) & 63, q = i & 15;
        uint4 v = ((const uint4*)((half ? g_x1l : g_x1h) + (size_t)p0 * 64))[row * 16 + q];
        *(uint4*)((half ? A2l : A2h) + row * A_STR + q * 16) = v;
    }
    if (tid < 64) { s_idx[tid] = load_idx(nn, p0 + tid); s_sum[tid] = 0.f; s_sq[tid] = 0.f; }
    s_g2[tid] = g2[tid]; s_be2[tid] = be2[tid]; s_b4[tid] = b4[tid];
    __syncthreads();

    const int wm = w >> 1, wn = w & 1;
    const uint32_t rA = (lane & 15), kO = (lane >> 4) * 16, nO = (lane >> 4) * 8;
    const uint32_t A2h_b = smem_u32(A2h), A2l_b = smem_u32(A2l);
    const uint32_t sWh_b = smem_u32(sWh), sWl_b = smem_u32(sWl);

    float acc[16][4];
    #pragma unroll
    for (int f = 0; f < 16; f++)
        #pragma unroll
        for (int q = 0; q < 4; q++) acc[f][q] = 0.f;

    // ---- GEMM1: D1[64x256] = x1 @ w3bot (warp: rows 16wm, cols 128wn) ----
    for (int kc = 0; kc < 4; kc++) {
        __syncthreads();
        for (int i = tid; i < 2048; i += 256) {
            int half = i >> 10, row = (i >> 5) & 31, q = i & 31;
            uint4 v = *(const uint4*)((const unsigned char*)(half ? (const void*)g_w3bl
                      : (const void*)g_w3bh) + (kc * 32 + row) * 512 + q * 16);
            *(uint4*)((half ? sWl : sWh) + row * W_STR + q * 16) = v;
        }
        __syncthreads();
        for (int ks2 = 0; ks2 < 2; ks2++) {
            uint32_t Ah[4], Al[4];
            uint32_t ro = (16 * wm + rA) * A_STR + kc * 64 + ks2 * 32 + kO;
            ldmA(Ah, A2h_b + ro);   // A1h aliased
            ldmA(Al, A2l_b + ro);
            #pragma unroll
            for (int g = 0; g < 4; g++) {
                uint32_t Bh[4][2], Bl[4][2];
                #pragma unroll
                for (int jj = 0; jj < 2; jj++) {
                    uint32_t ro2 = (ks2 * 16 + rA) * W_STR + (128 * wn + 32 * g + jj * 16 + nO) * 2;
                    ldmBT(&Bh[jj * 2][0], sWh_b + ro2);
                    ldmBT(&Bl[jj * 2][0], sWl_b + ro2);
                }
                #pragma unroll
                for (int f = 0; f < 4; f++) {
                    mma16816(acc[4 * g + f], Ah, Bh[f][0], Bh[f][1]);
                    mma16816(acc[4 * g + f], Ah, Bl[f][0], Bl[f][1]);
                    mma16816(acc[4 * g + f], Al, Bh[f][0], Bh[f][1]);
                }
            }
        }
    }
    __syncthreads();   // all A1 reads complete before A2 overwrites (alias)

    // ---- epilogue1: +z, stats, write A2 (pre-LN bf16 hi/lo) ----
    const int rr0 = 16 * wm + (lane >> 2), rr1 = rr0 + 8;
    const float* zb0 = g_z + ((size_t)b * CC + s_idx[rr0]) * 256;
    const float* zb1 = g_z + ((size_t)b * CC + s_idx[rr1]) * 256;
    {
        float sum0 = 0.f, sq0 = 0.f, sum1 = 0.f, sq1 = 0.f;
        #pragma unroll
        for (int f = 0; f < 16; f++) {
            int c = 128 * wn + 8 * f + 2 * (lane & 3);
            float2 z0 = *(const float2*)(zb0 + c);
            float2 z1 = *(const float2*)(zb1 + c);
            float v0 = acc[f][0] + z0.x, v1 = acc[f][1] + z0.y;
            float v2 = acc[f][2] + z1.x, v3 = acc[f][3] + z1.y;
            sum0 += v0 + v1; sq0 = fmaf(v0, v0, fmaf(v1, v1, sq0));
            sum1 += v2 + v3; sq1 = fmaf(v2, v2, fmaf(v3, v3, sq1));
            uint32_t ph, pl;
            bsplit(v0, v1, ph, pl);
            *(uint32_t*)(A2h + rr0 * A2_STR + c * 2) = ph;
            *(uint32_t*)(A2l + rr0 * A2_STR + c * 2) = pl;
            bsplit(v2, v3, ph, pl);
            *(uint32_t*)(A2h + rr1 * A2_STR + c * 2) = ph;
            *(uint32_t*)(A2l + rr1 * A2_STR + c * 2) = pl;
        }
        #pragma unroll
        for (int o = 1; o <= 2; o <<= 1) {
            sum0 += __shfl_xor_sync(0xffffffffu, sum0, o);
            sq0  += __shfl_xor_sync(0xffffffffu, sq0,  o);
            sum1 += __shfl_xor_sync(0xffffffffu, sum1, o);
            sq1  += __shfl_xor_sync(0xffffffffu, sq1,  o);
        }
        if ((lane & 3) == 0) {
            atomicAdd(&s_sum[rr0], sum0); atomicAdd(&s_sq[rr0], sq0);
            atomicAdd(&s_sum[rr1], sum1); atomicAdd(&s_sq[rr1], sq1);
        }
    }
    __syncthreads();

    // ---- LN + GELU in place on A2 (warp w: rows 8w..8w+7) ----
    for (int rl = 0; rl < 8; rl++) {
        int r = w * 8 + rl;
        float mu = s_sum[r] * (1.f / 256.f);
        float var = s_sq[r] * (1.f / 256.f) - mu * mu;
        float rstd = rsqrtf(var + 1e-5f);
        uint4* ph4 = (uint4*)(A2h + r * A2_STR + lane * 16);
        uint4* pl4 = (uint4*)(A2l + r * A2_STR + lane * 16);
        uint4 h4 = *ph4, l4 = *pl4;
        const uint32_t* hw = &h4.x;
        const uint32_t* lw = &l4.x;
        uint4 nh4, nl4;
        uint32_t* nhw = &nh4.x;
        uint32_t* nlw = &nl4.x;
        int c0 = lane * 8;
        #pragma unroll
        for (int p = 0; p < 4; p++) {
            float2 v = upk2(hw[p], lw[p]);
            int c = c0 + 2 * p;
            float t0 = gelu_exact((v.x - mu) * rstd * s_g2[c] + s_be2[c]);
            float t1 = gelu_exact((v.y - mu) * rstd * s_g2[c + 1] + s_be2[c + 1]);
            bsplit(t0, t1, nhw[p], nlw[p]);
        }
        *ph4 = nh4; *pl4 = nl4;
    }
    __syncthreads();

    // ---- GEMM2: D2[64x256] = h @ w4 ----
    #pragma unroll
    for (int f = 0; f < 16; f++)
        #pragma unroll
        for (int q = 0; q < 4; q++) acc[f][q] = 0.f;

    for (int kc = 0; kc < 8; kc++) {
        __syncthreads();
        for (int i = tid; i < 2048; i += 256) {
            int half = i >> 10, row = (i >> 5) & 31, q = i & 31;
            uint4 v = *(const uint4*)((const unsigned char*)(half ? (const void*)g_w4l
                      : (const void*)g_w4h) + (kc * 32 + row) * 512 + q * 16);
            *(uint4*)((half ? sWl : sWh) + row * W_STR + q * 16) = v;
        }
        __syncthreads();
        for (int ks2 = 0; ks2 < 2; ks2++) {
            uint32_t Ah[4], Al[4];
            uint32_t ro = (16 * wm + rA) * A2_STR + kc * 64 + ks2 * 32 + kO;
            ldmA(Ah, A2h_b + ro);
            ldmA(Al, A2l_b + ro);
            #pragma unroll
            for (int g = 0; g < 4; g++) {
                uint32_t Bh[4][2], Bl[4][2];
                #pragma unroll
                for (int jj = 0; jj < 2; jj++) {
                    uint32_t ro2 = (ks2 * 16 + rA) * W_STR + (128 * wn + 32 * g + jj * 16 + nO) * 2;
                    ldmBT(&Bh[jj * 2][0], sWh_b + ro2);
                    ldmBT(&Bl[jj * 2][0], sWl_b + ro2);
                }
                #pragma unroll
                for (int f = 0; f < 4; f++) {
                    mma16816(acc[4 * g + f], Ah, Bh[f][0], Bh[f][1]);
                    mma16816(acc[4 * g + f], Ah, Bl[f][0], Bl[f][1]);
                    mma16816(acc[4 * g + f], Al, Bh[f][0], Bh[f][1]);
                }
            }
        }
    }

    // ---- epilogue2: +b4, scatter-max ----
    {
        int* ob0 = (int*)(out + ((size_t)b * CC + s_idx[rr0]) * 256);
        int* ob1 = (int*)(out + ((size_t)b * CC + s_idx[rr1]) * 256);
        #pragma unroll
        for (int f = 0; f < 16; f++) {
            int c = 128 * wn + 8 * f + 2 * (lane & 3);
            float v0 = acc[f][0] + s_b4[c], v1 = acc[f][1] + s_b4[c + 1];
            float v2 = acc[f][2] + s_b4[c], v3 = acc[f][3] + s_b4[c + 1];
            if (v0 > 0.f) atomicMax(ob0 + c,     __float_as_int(v0));
            if (v1 > 0.f) atomicMax(ob0 + c + 1, __float_as_int(v1));
            if (v2 > 0.f) atomicMax(ob1 + c,     __float_as_int(v2));
            if (v3 > 0.f) atomicMax(ob1 + c + 1, __float_as_int(v3));
        }
    }
}

// ---------------------------------------------------------------------------
extern "C" void kernel_launch(void* const* d_in, const int* in_sizes, int n_in,
                              void* d_out, int out_size)
{
    const float* patches = (const float*)d_in[0];
    const void*  nn      = d_in[1];
    const float* w1  = (const float*)d_in[3];
    const float* b1  = (const float*)d_in[4];
    const float* g1  = (const float*)d_in[5];
    const float* be1 = (const float*)d_in[6];
    const float* w2  = (const float*)d_in[7];
    const float* b2  = (const float*)d_in[8];
    const float* w3  = (const float*)d_in[9];
    const float* b3  = (const float*)d_in[10];
    const float* g2  = (const float*)d_in[11];
    const float* be2 = (const float*)d_in[12];
    const float* w4  = (const float*)d_in[13];
    const float* b4  = (const float*)d_in[14];
    float* out = (float*)d_out;

    cudaFuncSetAttribute(k_conv1,  cudaFuncAttributeMaxDynamicSharedMemorySize, K1_SMEM);
    cudaFuncSetAttribute(k_center, cudaFuncAttributeMaxDynamicSharedMemorySize, KZ_SMEM);
    cudaFuncSetAttribute(k_conv2,  cudaFuncAttributeMaxDynamicSharedMemorySize, K2_SMEM);

    k_detect<<<1, 32>>>(nn);
    k_zero<<<512, 256>>>(out);
    k_prep<<<448, 256>>>(w2, w3, w4);
    k_conv1<<<NTB, 256, K1_SMEM>>>(patches, nn, w1, b1, g1, be1, b2);
    k_center<<<BB * CC / 64, 256, KZ_SMEM>>>(w3, b3);
    k_conv2<<<NTB, 256, K2_SMEM>>>(nn, g2, be2, b4, out);
}